// round 7
// baseline (speedup 1.0000x reference)
#include <cuda_runtime.h>
#include <cuda_bf16.h>
#include <cstdint>

// out = relu(x @ W_w^T + W_b)   (attention collapses: softmax rows sum to 1).
//
// R7: barrier-free mainloop.
//  - B (weight slice, 64x256) preloaded hi/lo to smem ONCE (1 barrier total).
//  - A fragments loaded DIRECTLY from gmem in mma layout (LDG.64, quad-coalesced)
//    and split to bf16 hi/lo in registers: no A STS/LDSM, no per-chunk barrier.
//  - R5 geometry kept (8 warps 4x2, warp tile 32x32, 2 CTA/SM) since R6 showed
//    low-occupancy 4-warp CTAs go latency-bound.

#define D_DIM 256
#define BM 128
#define BN 64
#define N_CHUNKS 8                     // K chunks of 32
#define ROWB_B 528                     // B smem row stride (256+8 bf16): conflict-free ldsm
#define BH_BYTES (BN * ROWB_B)         // 33792
#define OFF_BL BH_BYTES
#define SMEM_TOTAL (2 * BH_BYTES)      // 67584

__device__ __forceinline__ uint32_t smem_u32(const void* p) {
    uint32_t a;
    asm("{ .reg .u64 t; cvta.to.shared.u64 t, %1; cvt.u32.u64 %0, t; }" : "=r"(a) : "l"(p));
    return a;
}

__device__ __forceinline__ void ldsm_x4(uint32_t* r, uint32_t addr) {
    asm volatile("ldmatrix.sync.aligned.m8n8.x4.shared.b16 {%0,%1,%2,%3}, [%4];"
                 : "=r"(r[0]), "=r"(r[1]), "=r"(r[2]), "=r"(r[3]) : "r"(addr));
}

__device__ __forceinline__ void mma_bf16(float* d, const uint32_t* a, const uint32_t* b) {
    asm volatile("mma.sync.aligned.m16n8k16.row.col.f32.bf16.bf16.f32 "
                 "{%0,%1,%2,%3}, {%4,%5,%6,%7}, {%8,%9}, {%0,%1,%2,%3};"
                 : "+f"(d[0]), "+f"(d[1]), "+f"(d[2]), "+f"(d[3])
                 : "r"(a[0]), "r"(a[1]), "r"(a[2]), "r"(a[3]),
                   "r"(b[0]), "r"(b[1]));
}

// float2 -> bf16x2 hi + bf16x2 residual lo (packed u32 each)
__device__ __forceinline__ void cvt_pair(float2 v, uint32_t& h, uint32_t& lo) {
    __nv_bfloat162 hb = __floats2bfloat162_rn(v.x, v.y);
    float2 hf = __bfloat1622float2(hb);
    __nv_bfloat162 lb = __floats2bfloat162_rn(v.x - hf.x, v.y - hf.y);
    h  = *(uint32_t*)&hb;
    lo = *(uint32_t*)&lb;
}

// Split a float4 into bf16 hi + lo, store 8 B each (B preload only).
__device__ __forceinline__ void split_store(uint32_t hi_addr, uint32_t lo_addr, float4 v) {
    __nv_bfloat162 h0 = __floats2bfloat162_rn(v.x, v.y);
    __nv_bfloat162 h1 = __floats2bfloat162_rn(v.z, v.w);
    float2 f0 = __bfloat1622float2(h0);
    float2 f1 = __bfloat1622float2(h1);
    __nv_bfloat162 l0 = __floats2bfloat162_rn(v.x - f0.x, v.y - f0.y);
    __nv_bfloat162 l1 = __floats2bfloat162_rn(v.z - f1.x, v.w - f1.y);
    uint32_t h0u = *(uint32_t*)&h0, h1u = *(uint32_t*)&h1;
    uint32_t l0u = *(uint32_t*)&l0, l1u = *(uint32_t*)&l1;
    asm volatile("st.shared.v2.b32 [%0], {%1, %2};" :: "r"(hi_addr), "r"(h0u), "r"(h1u) : "memory");
    asm volatile("st.shared.v2.b32 [%0], {%1, %2};" :: "r"(lo_addr), "r"(l0u), "r"(l1u) : "memory");
}

__global__ __launch_bounds__(256, 2)
void fcgat_hmma(const float* __restrict__ A,     // x  [32768, 256]
                const float* __restrict__ W,     // W  [256, 256]
                const float* __restrict__ bias,  // [256]
                float* __restrict__ C)           // [32768, 256]
{
    extern __shared__ __align__(16) unsigned char smem[];
    const uint32_t sb = smem_u32(smem);

    const int t   = threadIdx.x;
    const int l   = t & 31;
    const int wid = t >> 5;
    const int wm  = wid & 3;          // 4 warps along M
    const int wn  = wid >> 2;         // 2 warps along N
    const int m0  = wm * 32;
    const int n0  = wn * 32;

    // ---- B preload: 64 rows x 64 float4 = 4096 -> 16/thread, hi/lo split ----
    const float* Bg = W + (size_t)blockIdx.x * BN * D_DIM;
    #pragma unroll
    for (int i = 0; i < 16; i++) {
        int idx = t + i * 256;
        int row = idx >> 6;            // 0..63
        int c4  = idx & 63;            // 0..63
        float4 v = *(const float4*)(Bg + (size_t)row * D_DIM + c4 * 4);
        uint32_t so = (uint32_t)(row * ROWB_B + c4 * 8);
        split_store(sb + so, sb + OFF_BL + so, v);
    }

    // Per-lane A base: row = blk*BM + m0 + (l>>2); frag rows at +0,+8 (and +16,+24 for i=1)
    const float* Alane = A + ((size_t)blockIdx.y * BM + m0 + (l >> 2)) * D_DIM + (l & 3) * 2;

    float acc[2][4][4];
    #pragma unroll
    for (int i = 0; i < 2; i++)
        #pragma unroll
        for (int j = 0; j < 4; j++)
            #pragma unroll
            for (int c = 0; c < 4; c++)
                acc[i][j][c] = 0.0f;

    const uint32_t b_lane = (uint32_t)((n0 + (l & 7) + ((l >> 4) << 3)) * ROWB_B
                                       + ((l >> 3) & 1) * 16);

    // f[i][ks][p]: p = {(r0,c0),(r1,c0),(r0,c1),(r1,c1)}, c1 = c0+8
    float2 f[2][2][4];

    #define LOAD_F(ch_) do {                                                       \
        const int c0_ = (ch_) * 32;                                                \
        _Pragma("unroll")                                                          \
        for (int i_ = 0; i_ < 2; i_++) {                                           \
            _Pragma("unroll")                                                      \
            for (int ks_ = 0; ks_ < 2; ks_++) {                                    \
                const float* p_ = Alane + (size_t)(i_ * 16) * D_DIM + c0_ + ks_ * 16; \
                f[i_][ks_][0] = *(const float2*)(p_);                              \
                f[i_][ks_][1] = *(const float2*)(p_ + 8 * D_DIM);                  \
                f[i_][ks_][2] = *(const float2*)(p_ + 8);                          \
                f[i_][ks_][3] = *(const float2*)(p_ + 8 * D_DIM + 8);              \
            }                                                                      \
        }                                                                          \
    } while (0)

    LOAD_F(0);              // chunk 0 in flight while B preload finishes
    __syncthreads();        // the ONLY barrier: B smem ready

    for (int ch = 0; ch < N_CHUNKS; ch++) {
        // convert current chunk's A to hi/lo fragments (frees f for prefetch)
        uint32_t ah[2][2][4], al[2][2][4];
        #pragma unroll
        for (int i = 0; i < 2; i++)
            #pragma unroll
            for (int ks = 0; ks < 2; ks++)
                #pragma unroll
                for (int p = 0; p < 4; p++)
                    cvt_pair(f[i][ks][p], ah[i][ks][p], al[i][ks][p]);

        // prefetch next chunk's A (latency hidden behind the 24 MMAs below)
        if (ch + 1 < N_CHUNKS) LOAD_F(ch + 1);

        #pragma unroll
        for (int ks = 0; ks < 2; ks++) {
            const uint32_t koB = (uint32_t)(ch * 64 + ks * 32);
            uint32_t bh[2][4], bl[2][4];
            #pragma unroll
            for (int jp = 0; jp < 2; jp++) {
                ldsm_x4(bh[jp], sb + b_lane + koB + jp * 16 * ROWB_B);
                ldsm_x4(bl[jp], sb + OFF_BL + b_lane + koB + jp * 16 * ROWB_B);
            }
            #pragma unroll
            for (int i = 0; i < 2; i++)
                #pragma unroll
                for (int j = 0; j < 4; j++) {
                    const uint32_t* bhf = bh[j >> 1] + (j & 1) * 2;
                    const uint32_t* blf = bl[j >> 1] + (j & 1) * 2;
                    mma_bf16(acc[i][j], ah[i][ks], bhf);   // xh * Wh
                    mma_bf16(acc[i][j], ah[i][ks], blf);   // xh * Wl
                    mma_bf16(acc[i][j], al[i][ks], bhf);   // xl * Wh
                }
        }
    }

    // ---- epilogue: bias + relu ----
    const int g  = l >> 2;
    const int tc = l & 3;
    #pragma unroll
    for (int i = 0; i < 2; i++) {
        const size_t r0 = (size_t)blockIdx.y * BM + m0 + 16 * i + g;
        const size_t r1 = r0 + 8;
        #pragma unroll
        for (int j = 0; j < 4; j++) {
            const int col = blockIdx.x * BN + n0 + 8 * j + 2 * tc;
            float2 bv = *(const float2*)(bias + col);
            float2 o0, o1;
            o0.x = fmaxf(acc[i][j][0] + bv.x, 0.0f);
            o0.y = fmaxf(acc[i][j][1] + bv.y, 0.0f);
            o1.x = fmaxf(acc[i][j][2] + bv.x, 0.0f);
            o1.y = fmaxf(acc[i][j][3] + bv.y, 0.0f);
            *(float2*)(C + r0 * D_DIM + col) = o0;
            *(float2*)(C + r1 * D_DIM + col) = o1;
        }
    }
}

extern "C" void kernel_launch(void* const* d_in, const int* in_sizes, int n_in,
                              void* d_out, int out_size)
{
    const float* x   = (const float*)d_in[0];
    const float* W_w = (const float*)d_in[1];
    const float* W_b = (const float*)d_in[2];
    float* out = (float*)d_out;

    int M = in_sizes[0] / D_DIM;                  // 32768
    cudaFuncSetAttribute(fcgat_hmma,
                         cudaFuncAttributeMaxDynamicSharedMemorySize, SMEM_TOTAL);
    dim3 grid(D_DIM / BN, M / BM);                // (4, 256) = 1024 CTAs
    fcgat_hmma<<<grid, 256, SMEM_TOTAL>>>(x, W_w, W_b, out);
}